// round 14
// baseline (speedup 1.0000x reference)
#include <cuda_runtime.h>
#include <cuda_bf16.h>
#include <cuda_fp16.h>
#include <math.h>
#include <stdint.h>

#define NQ   10001          // distinct quantized times: floor(t/0.1), t in [0,1000)
#define DD   1024
#define RR   256
#define QT   128            // q tile (build M)
#define DT   64             // d tile (build N)
#define NQT  10112          // 79 * 128 q-tiles
#define NQTILE 79
#define SPH  136            // padded bf16 smem row stride for K=128 stage (272 B)
#define NCHUNK 4
#define CCOLS 256           // output columns per chunk
#define BPC  316            // build CTAs per chunk (79 qtiles x 4 d-blocks)
#define SROWS 32            // scatter rows per CTA

#define RED_BLKS (NQT / 8)  // prep: one warp per q row, 8 rows/block
#define WE_BLKS  (DD / 8)

// Scratch (device globals — no allocation allowed)
__device__ __nv_bfloat16 g_redH[NQT * RR];
__device__ __nv_bfloat16 g_redL[NQT * RR];
__device__ __nv_bfloat16 g_WeH[DD * RR];
__device__ __nv_bfloat16 g_WeL[DD * RR];
__device__ __align__(128) __half g_table[NQ * DD];   // LUT [q][d], fp16, ~20.5 MB
__device__ int g_ready[NCHUNK * NQTILE];             // build completion counters

// smem offsets for the build role (two-stage K: 128 per stage, 2 CTAs/SM)
#define OFF_AH 0
#define OFF_AL (QT * SPH * 2)
#define OFF_BH (2 * QT * SPH * 2)
#define OFF_BL (2 * QT * SPH * 2 + DT * SPH * 2)
#define SMEM_MMA (2 * QT * SPH * 2 + 2 * DT * SPH * 2)   // 104448

// ---------------------------------------------------------------------------
__device__ __forceinline__ uint32_t smem_u32(const void* p) {
    uint32_t a;
    asm("{ .reg .u64 t; cvta.to.shared.u64 t, %1; cvt.u32.u64 %0, t; }"
        : "=r"(a) : "l"(p));
    return a;
}
__device__ __forceinline__ void ldm4(uint32_t* r, uint32_t addr) {
    asm volatile("ldmatrix.sync.aligned.m8n8.x4.shared.b16 {%0,%1,%2,%3}, [%4];"
                 : "=r"(r[0]), "=r"(r[1]), "=r"(r[2]), "=r"(r[3]) : "r"(addr));
}
__device__ __forceinline__ void mma_bf16(float* c, const uint32_t* a,
                                         uint32_t b0, uint32_t b1) {
    asm volatile(
        "mma.sync.aligned.m16n8k16.row.col.f32.bf16.bf16.f32 "
        "{%0,%1,%2,%3}, {%4,%5,%6,%7}, {%8,%9}, {%0,%1,%2,%3};"
        : "+f"(c[0]), "+f"(c[1]), "+f"(c[2]), "+f"(c[3])
        : "r"(a[0]), "r"(a[1]), "r"(a[2]), "r"(a[3]), "r"(b0), "r"(b1));
}
__device__ __forceinline__ float cos_mufu(float x) {
    float r;
    asm("cos.approx.f32 %0, %1;" : "=f"(r) : "f"(x));
    return r;
}
__device__ __forceinline__ uint32_t bf16_bits(float v) {
    return (uint32_t)__bfloat16_as_ushort(__float2bfloat16(v));
}
__device__ __forceinline__ int ld_acquire(const int* p) {
    int v;
    asm volatile("ld.global.acquire.gpu.b32 %0, [%1];" : "=r"(v) : "l"(p));
    return v;
}
__device__ __forceinline__ int qof(float tv) {
    int q = (int)floorf(__fdiv_rn(tv, 0.1f));   // IEEE div under any fast-math
    return max(0, min(q, NQ - 1));
}

// ---------------------------------------------------------------------------
// Prep (R13 proven): one warp per row; coalesced uint4 stores; also zeroes
// the readiness counters (visible to k_fused by stream order).
__global__ void __launch_bounds__(256) k_prep(const float* __restrict__ wr,
                                              const float* __restrict__ wrb,
                                              const float* __restrict__ we) {
    if (blockIdx.x == 0 && threadIdx.x < NCHUNK * NQTILE)
        g_ready[threadIdx.x] = 0;

    int blk  = blockIdx.x;
    int wid  = threadIdx.x >> 5;
    int lane = threadIdx.x & 31;
    int r0 = lane * 8;

    float v[8];
    size_t dst;
    if (blk < RED_BLKS) {
        int q  = blk * 8 + wid;
        int qc = min(q, NQ - 1);
        float tq = (float)qc * 0.1f;              // matches floor(t/0.1f)*0.1f
        float4 w0 = *(const float4*)(wr + r0);
        float4 w1 = *(const float4*)(wr + r0 + 4);
        float4 b0 = *(const float4*)(wrb + r0);
        float4 b1 = *(const float4*)(wrb + r0 + 4);
        float ws[8] = { w0.x, w0.y, w0.z, w0.w, w1.x, w1.y, w1.z, w1.w };
        float bs[8] = { b0.x, b0.y, b0.z, b0.w, b1.x, b1.y, b1.z, b1.w };
#pragma unroll
        for (int j = 0; j < 8; ++j) {
            float arg = fmaf(tq, ws[j], bs[j]);
            // Cody-Waite 2*pi reduction (|arg| <= ~153): exact under fast-math
            float k   = rintf(arg * 0.15915494309189535f);
            float red = fmaf(-k, 6.28125f, arg);
            red       = fmaf(-k, 1.9353071795864769e-3f, red);
            float c   = cos_mufu(red);
            v[j] = c > 0.0f ? c : 0.0f;
        }
        dst = (size_t)q * RR + r0;
    } else {
        int d = (blk - RED_BLKS) * 8 + wid;
        const float4* p = (const float4*)(we + (size_t)d * RR + r0);
        float4 x0 = p[0], x1 = p[1];
        v[0] = x0.x; v[1] = x0.y; v[2] = x0.z; v[3] = x0.w;
        v[4] = x1.x; v[5] = x1.y; v[6] = x1.z; v[7] = x1.w;
        dst = (size_t)d * RR + r0;
    }

    uint4 ph, pl;
    uint32_t* hh = (uint32_t*)&ph;
    uint32_t* ll = (uint32_t*)&pl;
#pragma unroll
    for (int j = 0; j < 4; ++j) {
        float a = v[2 * j], b = v[2 * j + 1];
        uint32_t ha = bf16_bits(a), hb = bf16_bits(b);
        float ra = a - __bfloat162float(__ushort_as_bfloat16((unsigned short)ha));
        float rb = b - __bfloat162float(__ushort_as_bfloat16((unsigned short)hb));
        hh[j] = ha | (hb << 16);
        ll[j] = bf16_bits(ra) | (bf16_bits(rb) << 16);
    }
    if (blockIdx.x < RED_BLKS) {
        *(uint4*)(g_redH + dst) = ph;
        *(uint4*)(g_redL + dst) = pl;
    } else {
        *(uint4*)(g_WeH + dst) = ph;
        *(uint4*)(g_WeL + dst) = pl;
    }
}

// ---------------------------------------------------------------------------
// Build role: one 128q x 64d tile (R13 proven body) + readiness signal.
__device__ void build_tile(const float* __restrict__ web, char* dsm,
                           int chunk, int idx) {
    __shared__ float sWeb[DT];
    uint32_t sb = smem_u32(dsm);
    int tid = threadIdx.x, lane = tid & 31, wid = tid >> 5;
    int qt  = idx >> 2;
    int qt0 = qt * QT;
    int dt0 = chunk * CCOLS + (idx & 3) * DT;

    if (tid < DT) sWeb[tid] = web[dt0 + tid];

    int wm = wid & 3, wn = wid >> 2;
    int lrow  = lane & 15;
    int khalf = (lane >> 4) * 8;

    uint32_t aHb = sb + OFF_AH + (uint32_t)((wm * 32 + lrow) * SPH + khalf) * 2;
    uint32_t aLb = sb + OFF_AL + (uint32_t)((wm * 32 + lrow) * SPH + khalf) * 2;
    uint32_t bHb = sb + OFF_BH + (uint32_t)((wn * 32 + lrow) * SPH + khalf) * 2;
    uint32_t bLb = sb + OFF_BL + (uint32_t)((wn * 32 + lrow) * SPH + khalf) * 2;

    float acc[2][4][4];
#pragma unroll
    for (int m = 0; m < 2; ++m)
#pragma unroll
        for (int j = 0; j < 4; ++j)
#pragma unroll
            for (int c = 0; c < 4; ++c) acc[m][j][c] = 0.0f;

    for (int h = 0; h < 2; ++h) {
#pragma unroll 4
        for (int i = tid; i < QT * 16; i += 256) {
            int row = i >> 4, u = i & 15;
            size_t   src = (size_t)(qt0 + row) * RR + h * 128 + u * 8;
            uint32_t dst = (uint32_t)(row * SPH + u * 8) * 2;
            *(uint4*)(dsm + OFF_AH + dst) = *(const uint4*)(g_redH + src);
            *(uint4*)(dsm + OFF_AL + dst) = *(const uint4*)(g_redL + src);
        }
#pragma unroll 2
        for (int i = tid; i < DT * 16; i += 256) {
            int row = i >> 4, u = i & 15;
            size_t   src = (size_t)(dt0 + row) * RR + h * 128 + u * 8;
            uint32_t dst = (uint32_t)(row * SPH + u * 8) * 2;
            *(uint4*)(dsm + OFF_BH + dst) = *(const uint4*)(g_WeH + src);
            *(uint4*)(dsm + OFF_BL + dst) = *(const uint4*)(g_WeL + src);
        }
        __syncthreads();

#pragma unroll
        for (int ks = 0; ks < 8; ++ks) {
            uint32_t ko = (uint32_t)(ks * 16) * 2;
            uint32_t aH[2][4], aL[2][4], bH[2][4], bL[2][4];
            ldm4(aH[0], aHb + ko);
            ldm4(aH[1], aHb + ko + 16 * SPH * 2);
            ldm4(aL[0], aLb + ko);
            ldm4(aL[1], aLb + ko + 16 * SPH * 2);
            ldm4(bH[0], bHb + ko);
            ldm4(bH[1], bHb + ko + 16 * SPH * 2);
            ldm4(bL[0], bLb + ko);
            ldm4(bL[1], bLb + ko + 16 * SPH * 2);
#pragma unroll
            for (int m = 0; m < 2; ++m) {
#pragma unroll
                for (int j = 0; j < 4; ++j) {
                    int g = j >> 1, p = j & 1;
                    mma_bf16(acc[m][j], aH[m], bH[g][p], bH[g][p + 2]);  // hh
                    mma_bf16(acc[m][j], aH[m], bL[g][p], bL[g][p + 2]);  // hl
                    mma_bf16(acc[m][j], aL[m], bH[g][p], bH[g][p + 2]);  // lh
                }
            }
        }
        __syncthreads();
    }

    int crow = lane >> 2;
    int ccol = (lane & 3) * 2;
#pragma unroll
    for (int m = 0; m < 2; ++m) {
        int r0 = qt0 + wm * 32 + m * 16 + crow;
#pragma unroll
        for (int j = 0; j < 4; ++j) {
            int cl = wn * 32 + j * 8 + ccol;
            float b0 = sWeb[cl], b1 = sWeb[cl + 1];
            if (r0 < NQ) {
                __half2 o = __floats2half2_rn(acc[m][j][0] + b0, acc[m][j][1] + b1);
                *(__half2*)(g_table + (size_t)r0 * DD + dt0 + cl) = o;
            }
            if (r0 + 8 < NQ) {
                __half2 o = __floats2half2_rn(acc[m][j][2] + b0, acc[m][j][3] + b1);
                *(__half2*)(g_table + (size_t)(r0 + 8) * DD + dt0 + cl) = o;
            }
        }
    }

    __syncthreads();
    if (tid == 0) {
        __threadfence();
        atomicAdd(&g_ready[chunk * NQTILE + qt], 1);
    }
}

// ---------------------------------------------------------------------------
// Scatter role: 32 rows x 256 cols (one chunk). 32 threads acquire-poll their
// row's qtile readiness in parallel, then all 256 threads copy (MLP=8).
__device__ void scatter_tile(const float* __restrict__ tt,
                             float4* __restrict__ out, int chunk, int idx) {
    __shared__ int qidx[SROWS];
    int tid = threadIdx.x;
    int b0  = idx * SROWS;

    if (tid < SROWS) {
        int q = qof(__ldg(tt + b0 + tid));
        qidx[tid] = q;
        const int* flag = &g_ready[chunk * NQTILE + (q >> 7)];
        while (ld_acquire(flag) < 4)
            asm volatile("nanosleep.u32 64;");
    }
    __syncthreads();

    int col = tid & 63;          // 64 threads per row; 8B (4 halves) each
    int rg  = tid >> 6;          // rows rg, rg+4, ..., rg+28
    uint2 v[8];
#pragma unroll
    for (int i = 0; i < 8; ++i) {
        int q = qidx[rg + 4 * i];
        v[i] = *(const uint2*)(g_table + (size_t)q * DD + (chunk << 8) + (col << 2));
    }
#pragma unroll
    for (int i = 0; i < 8; ++i) {
        int b = b0 + rg + 4 * i;
        float2 f01 = __half22float2(*(const __half2*)&v[i].x);
        float2 f23 = __half22float2(*(const __half2*)&v[i].y);
        float4 o = { f01.x, f01.y, f23.x, f23.y };
        __stcs(out + ((size_t)b * (DD / 4) + chunk * (CCOLS / 4) + col), o);
    }
}

// ---------------------------------------------------------------------------
// Fused kernel. Grid order: [b0][b1][s0][b2][s1][b3][s2][s3] — each build
// chunk k>=2 is dispatched a full scatter-chunk ahead of its consumer.
__global__ void __launch_bounds__(256) k_fused(const float* __restrict__ web,
                                               const float* __restrict__ tt,
                                               float4* __restrict__ out,
                                               int s) {   // scatter CTAs/chunk
    extern __shared__ char dsm[];
    int bid = blockIdx.x;
    if (bid < BPC)                     { build_tile(web, dsm, 0, bid); return; }
    bid -= BPC;
    if (bid < BPC)                     { build_tile(web, dsm, 1, bid); return; }
    bid -= BPC;
    if (bid < s)                       { scatter_tile(tt, out, 0, bid); return; }
    bid -= s;
    if (bid < BPC)                     { build_tile(web, dsm, 2, bid); return; }
    bid -= BPC;
    if (bid < s)                       { scatter_tile(tt, out, 1, bid); return; }
    bid -= s;
    if (bid < BPC)                     { build_tile(web, dsm, 3, bid); return; }
    bid -= BPC;
    if (bid < s)                       { scatter_tile(tt, out, 2, bid); return; }
    bid -= s;
    scatter_tile(tt, out, 3, bid);
}

// ---------------------------------------------------------------------------
extern "C" void kernel_launch(void* const* d_in, const int* in_sizes, int n_in,
                              void* d_out, int out_size) {
    const float* t   = (const float*)d_in[0];   // (B,)
    const float* wr  = (const float*)d_in[1];   // (R,1)
    const float* wrb = (const float*)d_in[2];   // (R,)
    const float* we  = (const float*)d_in[3];   // (D,R)
    const float* web = (const float*)d_in[4];   // (D,)
    float* out = (float*)d_out;
    int B = in_sizes[0];
    int s = B / SROWS;                           // scatter CTAs per chunk

    cudaFuncSetAttribute(k_fused,
                         cudaFuncAttributeMaxDynamicSharedMemorySize, SMEM_MMA);

    k_prep<<<RED_BLKS + WE_BLKS, 256>>>(wr, wrb, we);
    k_fused<<<NCHUNK * BPC + NCHUNK * s, 256, SMEM_MMA>>>(web, t, (float4*)out, s);
}

// round 15
// speedup vs baseline: 1.6888x; 1.6888x over previous
#include <cuda_runtime.h>
#include <cuda_bf16.h>
#include <cuda_fp16.h>
#include <math.h>
#include <stdint.h>

#define NQ   10001          // distinct quantized times: floor(t/0.1), t in [0,1000)
#define DD   1024
#define RR   256
#define QT   128            // q tile (build M)
#define DT   64             // d tile (build N)
#define NQT  10112          // 79 * 128 q-tiles
#define ROWS_PER_BLK 8      // scatter rows per block (proven)
#define SPH  136            // padded bf16 smem row stride for K=128 stage (272 B)

// Scratch (device globals — no allocation allowed)
__device__ __align__(128) __half g_table[NQ * DD];   // LUT [q][d], fp16, ~20.5 MB

// smem offsets for the build kernel (two-stage K: 128 per stage, 2 CTAs/SM)
#define OFF_AH 0
#define OFF_AL (QT * SPH * 2)                 // 34816
#define OFF_BH (2 * QT * SPH * 2)             // 69632
#define OFF_BL (2 * QT * SPH * 2 + DT * SPH * 2)
#define SMEM_MMA (2 * QT * SPH * 2 + 2 * DT * SPH * 2)   // 104448

// ---------------------------------------------------------------------------
__device__ __forceinline__ uint32_t smem_u32(const void* p) {
    uint32_t a;
    asm("{ .reg .u64 t; cvta.to.shared.u64 t, %1; cvt.u32.u64 %0, t; }"
        : "=r"(a) : "l"(p));
    return a;
}
__device__ __forceinline__ void ldm4(uint32_t* r, uint32_t addr) {
    asm volatile("ldmatrix.sync.aligned.m8n8.x4.shared.b16 {%0,%1,%2,%3}, [%4];"
                 : "=r"(r[0]), "=r"(r[1]), "=r"(r[2]), "=r"(r[3]) : "r"(addr));
}
__device__ __forceinline__ void mma_bf16(float* c, const uint32_t* a,
                                         uint32_t b0, uint32_t b1) {
    asm volatile(
        "mma.sync.aligned.m16n8k16.row.col.f32.bf16.bf16.f32 "
        "{%0,%1,%2,%3}, {%4,%5,%6,%7}, {%8,%9}, {%0,%1,%2,%3};"
        : "+f"(c[0]), "+f"(c[1]), "+f"(c[2]), "+f"(c[3])
        : "r"(a[0]), "r"(a[1]), "r"(a[2]), "r"(a[3]), "r"(b0), "r"(b1));
}
// MUFU cosine (hardware SFU): ~4e-7 abs error on |x| <= pi; we always reduce first.
__device__ __forceinline__ float cos_mufu(float x) {
    float r;
    asm("cos.approx.f32 %0, %1;" : "=f"(r) : "f"(x));
    return r;
}
__device__ __forceinline__ uint32_t bf16_bits(float v) {
    return (uint32_t)__bfloat16_as_ushort(__float2bfloat16(v));
}
// Split 8 fp32 values into packed bf16 hi (uint4) and lo-residual (uint4).
__device__ __forceinline__ void split8(const float* v, uint4& ph, uint4& pl) {
    uint32_t* hh = (uint32_t*)&ph;
    uint32_t* ll = (uint32_t*)&pl;
#pragma unroll
    for (int j = 0; j < 4; ++j) {
        float a = v[2 * j], b = v[2 * j + 1];
        uint32_t ha = bf16_bits(a), hb = bf16_bits(b);
        float ra = a - __bfloat162float(__ushort_as_bfloat16((unsigned short)ha));
        float rb = b - __bfloat162float(__ushort_as_bfloat16((unsigned short)hb));
        hh[j] = ha | (hb << 16);
        ll[j] = bf16_bits(ra) | (bf16_bits(rb) << 16);
    }
}

// ---------------------------------------------------------------------------
// HMMA table build with INLINE operand prep (no prep kernel, no A gmem pass):
// per K-stage, the cos/relu A tile and the fp32->split-bf16 B tile are
// computed/loaded directly into padded smem. Two-stage K (2 CTAs/SM).
// 8 warps (4m x 2n); warp tile 32q x 32d; 3 split-bf16 products (hh+hl+lh).
// grid (79, 16), 256 threads.
__global__ void __launch_bounds__(256) k_mma_table(const float* __restrict__ wr,
                                                   const float* __restrict__ wrb,
                                                   const float* __restrict__ we,
                                                   const float* __restrict__ web) {
    extern __shared__ char dsm[];
    __shared__ float sWeb[DT];
    __shared__ float sWr[RR], sWrb[RR];
    uint32_t sb = smem_u32(dsm);
    int tid = threadIdx.x, lane = tid & 31, wid = tid >> 5;
    int qt0 = blockIdx.x * QT, dt0 = blockIdx.y * DT;

    if (tid < DT)  sWeb[tid] = web[dt0 + tid];
    if (tid < RR)  { sWr[tid] = wr[tid]; sWrb[tid] = wrb[tid]; }
    __syncthreads();

    int wm = wid & 3, wn = wid >> 2;
    int lrow  = lane & 15;
    int khalf = (lane >> 4) * 8;

    uint32_t aHb = sb + OFF_AH + (uint32_t)((wm * 32 + lrow) * SPH + khalf) * 2;
    uint32_t aLb = sb + OFF_AL + (uint32_t)((wm * 32 + lrow) * SPH + khalf) * 2;
    uint32_t bHb = sb + OFF_BH + (uint32_t)((wn * 32 + lrow) * SPH + khalf) * 2;
    uint32_t bLb = sb + OFF_BL + (uint32_t)((wn * 32 + lrow) * SPH + khalf) * 2;

    float acc[2][4][4];
#pragma unroll
    for (int m = 0; m < 2; ++m)
#pragma unroll
        for (int j = 0; j < 4; ++j)
#pragma unroll
            for (int c = 0; c < 4; ++c) acc[m][j][c] = 0.0f;

    for (int h = 0; h < 2; ++h) {
        if (h) __syncthreads();            // protect smem reuse across stages

        // A stage: compute relu(cos(tq*wr+wrb)) for rows qt0..+127, k half h,
        // split to bf16 hi/lo, store 16B packs. 8 tasks/thread, 8 cos each.
#pragma unroll
        for (int i = tid; i < QT * 16; i += 256) {
            int row = i >> 4, u = i & 15;
            int qc = min(qt0 + row, NQ - 1);      // pad rows clamped (never stored)
            float tq = (float)qc * 0.1f;          // matches floor(t/0.1f)*0.1f
            int r0 = h * 128 + u * 8;
            float v[8];
#pragma unroll
            for (int j = 0; j < 8; ++j) {
                float arg = fmaf(tq, sWr[r0 + j], sWrb[r0 + j]);
                // Cody-Waite 2*pi reduction (|arg| <= ~153): exact under fast-math
                float k   = rintf(arg * 0.15915494309189535f);
                float red = fmaf(-k, 6.28125f, arg);
                red       = fmaf(-k, 1.9353071795864769e-3f, red);
                float c   = cos_mufu(red);
                v[j] = c > 0.0f ? c : 0.0f;
            }
            uint4 ph, pl;
            split8(v, ph, pl);
            uint32_t dst = (uint32_t)(row * SPH + u * 8) * 2;
            *(uint4*)(dsm + OFF_AH + dst) = ph;
            *(uint4*)(dsm + OFF_AL + dst) = pl;
        }

        // B stage: load we fp32 rows dt0..+63, k half h; split inline.
#pragma unroll
        for (int i = tid; i < DT * 16; i += 256) {
            int row = i >> 4, u = i & 15;
            const float4* p = (const float4*)(we + (size_t)(dt0 + row) * RR
                                              + h * 128 + u * 8);
            float4 x0 = p[0], x1 = p[1];
            float v[8] = { x0.x, x0.y, x0.z, x0.w, x1.x, x1.y, x1.z, x1.w };
            uint4 ph, pl;
            split8(v, ph, pl);
            uint32_t dst = (uint32_t)(row * SPH + u * 8) * 2;
            *(uint4*)(dsm + OFF_BH + dst) = ph;
            *(uint4*)(dsm + OFF_BL + dst) = pl;
        }
        __syncthreads();

#pragma unroll
        for (int ks = 0; ks < 8; ++ks) {
            uint32_t ko = (uint32_t)(ks * 16) * 2;
            uint32_t aH[2][4], aL[2][4], bH[2][4], bL[2][4];
            ldm4(aH[0], aHb + ko);
            ldm4(aH[1], aHb + ko + 16 * SPH * 2);
            ldm4(aL[0], aLb + ko);
            ldm4(aL[1], aLb + ko + 16 * SPH * 2);
            ldm4(bH[0], bHb + ko);
            ldm4(bH[1], bHb + ko + 16 * SPH * 2);
            ldm4(bL[0], bLb + ko);
            ldm4(bL[1], bLb + ko + 16 * SPH * 2);
#pragma unroll
            for (int m = 0; m < 2; ++m) {
#pragma unroll
                for (int j = 0; j < 4; ++j) {
                    int g = j >> 1, p = j & 1;
                    mma_bf16(acc[m][j], aH[m], bH[g][p], bH[g][p + 2]);  // hh
                    mma_bf16(acc[m][j], aH[m], bL[g][p], bL[g][p + 2]);  // hl
                    mma_bf16(acc[m][j], aL[m], bH[g][p], bH[g][p + 2]);  // lh
                }
            }
        }
    }

    // Epilogue: +bias, convert to fp16, half2 stores.
    int crow = lane >> 2;
    int ccol = (lane & 3) * 2;
#pragma unroll
    for (int m = 0; m < 2; ++m) {
        int r0 = qt0 + wm * 32 + m * 16 + crow;
#pragma unroll
        for (int j = 0; j < 4; ++j) {
            int cl = wn * 32 + j * 8 + ccol;
            float b0 = sWeb[cl], b1 = sWeb[cl + 1];
            if (r0 < NQ) {
                __half2 o = __floats2half2_rn(acc[m][j][0] + b0, acc[m][j][1] + b1);
                *(__half2*)(g_table + (size_t)r0 * DD + dt0 + cl) = o;
            }
            if (r0 + 8 < NQ) {
                __half2 o = __floats2half2_rn(acc[m][j][2] + b0, acc[m][j][3] + b1);
                *(__half2*)(g_table + (size_t)(r0 + 8) * DD + dt0 + cl) = o;
            }
        }
    }
}

// ---------------------------------------------------------------------------
// Scatter (proven form): out[b][:] = fp32(table_fp16[q(b)][:])
// 8 rows/block, 256 threads; 8 independent 8B loads, cvt, 8 STG.128 streaming.
__global__ void __launch_bounds__(256) k_scatter(const float* __restrict__ tt,
                                                 float4* __restrict__ out) {
    __shared__ int qidx[ROWS_PER_BLK];
    int b0 = blockIdx.x * ROWS_PER_BLK;
    if (threadIdx.x < ROWS_PER_BLK) {
        float tv = __ldg(tt + b0 + threadIdx.x);
        int q = (int)floorf(__fdiv_rn(tv, 0.1f));   // IEEE div under any fast-math
        qidx[threadIdx.x] = max(0, min(q, NQ - 1));
    }
    __syncthreads();

    const uint2* tab = (const uint2*)g_table;       // 4 halves per uint2
    uint2 v[ROWS_PER_BLK];
#pragma unroll
    for (int i = 0; i < ROWS_PER_BLK; ++i)
        v[i] = tab[(size_t)qidx[i] * (DD / 4) + threadIdx.x];
#pragma unroll
    for (int i = 0; i < ROWS_PER_BLK; ++i) {
        float2 f01 = __half22float2(*(const __half2*)&v[i].x);
        float2 f23 = __half22float2(*(const __half2*)&v[i].y);
        float4 o = { f01.x, f01.y, f23.x, f23.y };
        __stcs(out + ((size_t)(b0 + i) * (DD / 4) + threadIdx.x), o);
    }
}

// ---------------------------------------------------------------------------
extern "C" void kernel_launch(void* const* d_in, const int* in_sizes, int n_in,
                              void* d_out, int out_size) {
    const float* t   = (const float*)d_in[0];   // (B,)
    const float* wr  = (const float*)d_in[1];   // (R,1)
    const float* wrb = (const float*)d_in[2];   // (R,)
    const float* we  = (const float*)d_in[3];   // (D,R)
    const float* web = (const float*)d_in[4];   // (D,)
    float* out = (float*)d_out;
    int B = in_sizes[0];

    cudaFuncSetAttribute(k_mma_table,
                         cudaFuncAttributeMaxDynamicSharedMemorySize, SMEM_MMA);

    k_mma_table<<<dim3(NQT / QT, DD / DT), 256, SMEM_MMA>>>(wr, wrb, we, web);
    k_scatter<<<B / ROWS_PER_BLK, 256>>>(t, (float4*)out);
}

// round 16
// speedup vs baseline: 1.8462x; 1.0932x over previous
#include <cuda_runtime.h>
#include <cuda_bf16.h>
#include <cuda_fp16.h>
#include <math.h>
#include <stdint.h>

#define NQ   10001          // distinct quantized times: floor(t/0.1), t in [0,1000)
#define DD   1024
#define RR   256
#define QT   128            // q tile (build M)
#define DT   64             // d tile (build N)
#define NQT  10112          // 79 * 128 q-tiles
#define ROWS_PER_BLK 8      // scatter rows per block (proven)
#define SP2  72             // padded bf16 smem row stride for K=64 stage (144 B)

#define RED_BLKS (NQT / 8)  // prep: one warp per q row, 8 rows/block
#define WE_BLKS  (DD / 8)

// Scratch (device globals — no allocation allowed)
__device__ __nv_bfloat16 g_redH[NQT * RR];
__device__ __nv_bfloat16 g_redL[NQT * RR];
__device__ __nv_bfloat16 g_WeH[DD * RR];
__device__ __nv_bfloat16 g_WeL[DD * RR];
__device__ __align__(128) __half g_table[NQ * DD];   // LUT [q][d], fp16, ~20.5 MB

// smem offsets for the build kernel (four-stage K: 64 per stage, 3 CTAs/SM)
#define OFF_AH 0
#define OFF_AL (QT * SP2 * 2)                 // 18432
#define OFF_BH (2 * QT * SP2 * 2)             // 36864
#define OFF_BL (2 * QT * SP2 * 2 + DT * SP2 * 2)   // 46080
#define SMEM_MMA (2 * QT * SP2 * 2 + 2 * DT * SP2 * 2)   // 55296

// ---------------------------------------------------------------------------
__device__ __forceinline__ uint32_t smem_u32(const void* p) {
    uint32_t a;
    asm("{ .reg .u64 t; cvta.to.shared.u64 t, %1; cvt.u32.u64 %0, t; }"
        : "=r"(a) : "l"(p));
    return a;
}
__device__ __forceinline__ void ldm4(uint32_t* r, uint32_t addr) {
    asm volatile("ldmatrix.sync.aligned.m8n8.x4.shared.b16 {%0,%1,%2,%3}, [%4];"
                 : "=r"(r[0]), "=r"(r[1]), "=r"(r[2]), "=r"(r[3]) : "r"(addr));
}
__device__ __forceinline__ void mma_bf16(float* c, const uint32_t* a,
                                         uint32_t b0, uint32_t b1) {
    asm volatile(
        "mma.sync.aligned.m16n8k16.row.col.f32.bf16.bf16.f32 "
        "{%0,%1,%2,%3}, {%4,%5,%6,%7}, {%8,%9}, {%0,%1,%2,%3};"
        : "+f"(c[0]), "+f"(c[1]), "+f"(c[2]), "+f"(c[3])
        : "r"(a[0]), "r"(a[1]), "r"(a[2]), "r"(a[3]), "r"(b0), "r"(b1));
}
// MUFU cosine (hardware SFU): ~4e-7 abs error on |x| <= pi; we always reduce first.
__device__ __forceinline__ float cos_mufu(float x) {
    float r;
    asm("cos.approx.f32 %0, %1;" : "=f"(r) : "f"(x));
    return r;
}
__device__ __forceinline__ uint32_t bf16_bits(float v) {
    return (uint32_t)__bfloat16_as_ushort(__float2bfloat16(v));
}

// ---------------------------------------------------------------------------
// Prep (R13 proven): one warp per row; lane computes 8 consecutive r,
// packs bf16x2, stores one uint4 per array (512 B/warp stores).
__global__ void __launch_bounds__(256) k_prep(const float* __restrict__ wr,
                                              const float* __restrict__ wrb,
                                              const float* __restrict__ we) {
    int blk  = blockIdx.x;
    int wid  = threadIdx.x >> 5;
    int lane = threadIdx.x & 31;
    int r0 = lane * 8;

    float v[8];
    size_t dst;
    if (blk < RED_BLKS) {
        int q  = blk * 8 + wid;
        int qc = min(q, NQ - 1);                  // pad rows clamped (never stored)
        float tq = (float)qc * 0.1f;              // matches floor(t/0.1f)*0.1f
        float4 w0 = *(const float4*)(wr + r0);
        float4 w1 = *(const float4*)(wr + r0 + 4);
        float4 b0 = *(const float4*)(wrb + r0);
        float4 b1 = *(const float4*)(wrb + r0 + 4);
        float ws[8] = { w0.x, w0.y, w0.z, w0.w, w1.x, w1.y, w1.z, w1.w };
        float bs[8] = { b0.x, b0.y, b0.z, b0.w, b1.x, b1.y, b1.z, b1.w };
#pragma unroll
        for (int j = 0; j < 8; ++j) {
            float arg = fmaf(tq, ws[j], bs[j]);
            // Cody-Waite 2*pi reduction (|arg| <= ~153): exact under fast-math
            float k   = rintf(arg * 0.15915494309189535f);
            float red = fmaf(-k, 6.28125f, arg);
            red       = fmaf(-k, 1.9353071795864769e-3f, red);
            float c   = cos_mufu(red);
            v[j] = c > 0.0f ? c : 0.0f;
        }
        dst = (size_t)q * RR + r0;
    } else {
        int d = (blk - RED_BLKS) * 8 + wid;
        const float4* p = (const float4*)(we + (size_t)d * RR + r0);
        float4 x0 = p[0], x1 = p[1];
        v[0] = x0.x; v[1] = x0.y; v[2] = x0.z; v[3] = x0.w;
        v[4] = x1.x; v[5] = x1.y; v[6] = x1.z; v[7] = x1.w;
        dst = (size_t)d * RR + r0;
    }

    uint4 ph, pl;
    uint32_t* hh = (uint32_t*)&ph;
    uint32_t* ll = (uint32_t*)&pl;
#pragma unroll
    for (int j = 0; j < 4; ++j) {
        float a = v[2 * j], b = v[2 * j + 1];
        uint32_t ha = bf16_bits(a), hb = bf16_bits(b);
        float ra = a - __bfloat162float(__ushort_as_bfloat16((unsigned short)ha));
        float rb = b - __bfloat162float(__ushort_as_bfloat16((unsigned short)hb));
        hh[j] = ha | (hb << 16);
        ll[j] = bf16_bits(ra) | (bf16_bits(rb) << 16);
    }
    if (blockIdx.x < RED_BLKS) {
        *(uint4*)(g_redH + dst) = ph;
        *(uint4*)(g_redL + dst) = pl;
    } else {
        *(uint4*)(g_WeH + dst) = ph;
        *(uint4*)(g_WeL + dst) = pl;
    }
}

// ---------------------------------------------------------------------------
// HMMA table build: FOUR-stage K staging (55 KB smem -> 3 CTAs/SM for better
// load/MMA overlap across CTAs). 8 warps (4m x 2n); warp tile 32q x 32d;
// 3 split-bf16 products (hh+hl+lh). grid (79, 16), 256 threads.
__global__ void __launch_bounds__(256) k_mma_table(const float* __restrict__ web) {
    extern __shared__ char dsm[];
    __shared__ float sWeb[DT];
    uint32_t sb = smem_u32(dsm);
    int tid = threadIdx.x, lane = tid & 31, wid = tid >> 5;
    int qt0 = blockIdx.x * QT, dt0 = blockIdx.y * DT;

    if (tid < DT) sWeb[tid] = web[dt0 + tid];

    int wm = wid & 3, wn = wid >> 2;
    int lrow  = lane & 15;
    int khalf = (lane >> 4) * 8;

    uint32_t aHb = sb + OFF_AH + (uint32_t)((wm * 32 + lrow) * SP2 + khalf) * 2;
    uint32_t aLb = sb + OFF_AL + (uint32_t)((wm * 32 + lrow) * SP2 + khalf) * 2;
    uint32_t bHb = sb + OFF_BH + (uint32_t)((wn * 32 + lrow) * SP2 + khalf) * 2;
    uint32_t bLb = sb + OFF_BL + (uint32_t)((wn * 32 + lrow) * SP2 + khalf) * 2;

    float acc[2][4][4];
#pragma unroll
    for (int m = 0; m < 2; ++m)
#pragma unroll
        for (int j = 0; j < 4; ++j)
#pragma unroll
            for (int c = 0; c < 4; ++c) acc[m][j][c] = 0.0f;

    for (int h = 0; h < 4; ++h) {
        if (h) __syncthreads();            // protect smem reuse across stages

        // stage K quarter h: A 128x64 (H/L), B 64x64 (H/L)
#pragma unroll 4
        for (int i = tid; i < QT * 8; i += 256) {
            int row = i >> 3, u = i & 7;
            size_t   src = (size_t)(qt0 + row) * RR + h * 64 + u * 8;
            uint32_t dst = (uint32_t)(row * SP2 + u * 8) * 2;
            *(uint4*)(dsm + OFF_AH + dst) = *(const uint4*)(g_redH + src);
            *(uint4*)(dsm + OFF_AL + dst) = *(const uint4*)(g_redL + src);
        }
#pragma unroll 2
        for (int i = tid; i < DT * 8; i += 256) {
            int row = i >> 3, u = i & 7;
            size_t   src = (size_t)(dt0 + row) * RR + h * 64 + u * 8;
            uint32_t dst = (uint32_t)(row * SP2 + u * 8) * 2;
            *(uint4*)(dsm + OFF_BH + dst) = *(const uint4*)(g_WeH + src);
            *(uint4*)(dsm + OFF_BL + dst) = *(const uint4*)(g_WeL + src);
        }
        __syncthreads();

#pragma unroll
        for (int ks = 0; ks < 4; ++ks) {
            uint32_t ko = (uint32_t)(ks * 16) * 2;
            uint32_t aH[2][4], aL[2][4], bH[2][4], bL[2][4];
            ldm4(aH[0], aHb + ko);
            ldm4(aH[1], aHb + ko + 16 * SP2 * 2);
            ldm4(aL[0], aLb + ko);
            ldm4(aL[1], aLb + ko + 16 * SP2 * 2);
            ldm4(bH[0], bHb + ko);
            ldm4(bH[1], bHb + ko + 16 * SP2 * 2);
            ldm4(bL[0], bLb + ko);
            ldm4(bL[1], bLb + ko + 16 * SP2 * 2);
#pragma unroll
            for (int m = 0; m < 2; ++m) {
#pragma unroll
                for (int j = 0; j < 4; ++j) {
                    int g = j >> 1, p = j & 1;
                    mma_bf16(acc[m][j], aH[m], bH[g][p], bH[g][p + 2]);  // hh
                    mma_bf16(acc[m][j], aH[m], bL[g][p], bL[g][p + 2]);  // hl
                    mma_bf16(acc[m][j], aL[m], bH[g][p], bH[g][p + 2]);  // lh
                }
            }
        }
    }

    // Epilogue: +bias, convert to fp16, half2 stores.
    int crow = lane >> 2;
    int ccol = (lane & 3) * 2;
#pragma unroll
    for (int m = 0; m < 2; ++m) {
        int r0 = qt0 + wm * 32 + m * 16 + crow;
#pragma unroll
        for (int j = 0; j < 4; ++j) {
            int cl = wn * 32 + j * 8 + ccol;
            float b0 = sWeb[cl], b1 = sWeb[cl + 1];
            if (r0 < NQ) {
                __half2 o = __floats2half2_rn(acc[m][j][0] + b0, acc[m][j][1] + b1);
                *(__half2*)(g_table + (size_t)r0 * DD + dt0 + cl) = o;
            }
            if (r0 + 8 < NQ) {
                __half2 o = __floats2half2_rn(acc[m][j][2] + b0, acc[m][j][3] + b1);
                *(__half2*)(g_table + (size_t)(r0 + 8) * DD + dt0 + cl) = o;
            }
        }
    }
}

// ---------------------------------------------------------------------------
// Scatter (proven form): out[b][:] = fp32(table_fp16[q(b)][:])
// 8 rows/block, 256 threads; 8 independent 8B loads, cvt, 8 STG.128 streaming.
__global__ void __launch_bounds__(256) k_scatter(const float* __restrict__ tt,
                                                 float4* __restrict__ out) {
    __shared__ int qidx[ROWS_PER_BLK];
    int b0 = blockIdx.x * ROWS_PER_BLK;
    if (threadIdx.x < ROWS_PER_BLK) {
        float tv = __ldg(tt + b0 + threadIdx.x);
        int q = (int)floorf(__fdiv_rn(tv, 0.1f));   // IEEE div under any fast-math
        qidx[threadIdx.x] = max(0, min(q, NQ - 1));
    }
    __syncthreads();

    const uint2* tab = (const uint2*)g_table;       // 4 halves per uint2
    uint2 v[ROWS_PER_BLK];
#pragma unroll
    for (int i = 0; i < ROWS_PER_BLK; ++i)
        v[i] = tab[(size_t)qidx[i] * (DD / 4) + threadIdx.x];
#pragma unroll
    for (int i = 0; i < ROWS_PER_BLK; ++i) {
        float2 f01 = __half22float2(*(const __half2*)&v[i].x);
        float2 f23 = __half22float2(*(const __half2*)&v[i].y);
        float4 o = { f01.x, f01.y, f23.x, f23.y };
        __stcs(out + ((size_t)(b0 + i) * (DD / 4) + threadIdx.x), o);
    }
}

// ---------------------------------------------------------------------------
extern "C" void kernel_launch(void* const* d_in, const int* in_sizes, int n_in,
                              void* d_out, int out_size) {
    const float* t   = (const float*)d_in[0];   // (B,)
    const float* wr  = (const float*)d_in[1];   // (R,1)
    const float* wrb = (const float*)d_in[2];   // (R,)
    const float* we  = (const float*)d_in[3];   // (D,R)
    const float* web = (const float*)d_in[4];   // (D,)
    float* out = (float*)d_out;
    int B = in_sizes[0];

    cudaFuncSetAttribute(k_mma_table,
                         cudaFuncAttributeMaxDynamicSharedMemorySize, SMEM_MMA);

    k_prep<<<RED_BLKS + WE_BLKS, 256>>>(wr, wrb, we);
    k_mma_table<<<dim3(NQT / QT, DD / DT), 256, SMEM_MMA>>>(web);
    k_scatter<<<B / ROWS_PER_BLK, 256>>>(t, (float4*)out);
}

// round 17
// speedup vs baseline: 2.1248x; 1.1509x over previous
#include <cuda_runtime.h>
#include <cuda_fp16.h>
#include <math.h>
#include <stdint.h>

#define NQ   10001          // distinct quantized times: floor(t/0.1), t in [0,1000)
#define DD   1024
#define RR   256
#define QT   128            // q tile (build M)
#define DT   64             // d tile (build N)
#define NQT  10112          // 79 * 128 q-tiles
#define ROWS_PER_BLK 8      // scatter rows per block (proven)
#define SP2  72             // padded fp16 smem row stride for K=64 stage (144 B)

#define RED_BLKS (NQT / 8)  // prep: one warp per q row, 8 rows/block
#define WE_BLKS  (DD / 8)

// Scratch (device globals — no allocation allowed)
__device__ __half g_redF[NQT * RR];                  // fp16 relu(cos) [q][r]
__device__ __half g_WeF[DD * RR];                    // fp16 w_expand [d][r]
__device__ __align__(128) __half g_table[NQ * DD];   // LUT [q][d], fp16, ~20.5 MB

// smem offsets for the build kernel (four-stage K=64; ~28 KB -> 4 CTAs/SM)
#define OFF_A 0
#define OFF_B (QT * SP2 * 2)                   // 18432
#define SMEM_MMA ((QT + DT) * SP2 * 2)         // 27648

// ---------------------------------------------------------------------------
__device__ __forceinline__ uint32_t smem_u32(const void* p) {
    uint32_t a;
    asm("{ .reg .u64 t; cvta.to.shared.u64 t, %1; cvt.u32.u64 %0, t; }"
        : "=r"(a) : "l"(p));
    return a;
}
__device__ __forceinline__ void ldm4(uint32_t* r, uint32_t addr) {
    asm volatile("ldmatrix.sync.aligned.m8n8.x4.shared.b16 {%0,%1,%2,%3}, [%4];"
                 : "=r"(r[0]), "=r"(r[1]), "=r"(r[2]), "=r"(r[3]) : "r"(addr));
}
__device__ __forceinline__ void mma_f16(float* c, const uint32_t* a,
                                        uint32_t b0, uint32_t b1) {
    asm volatile(
        "mma.sync.aligned.m16n8k16.row.col.f32.f16.f16.f32 "
        "{%0,%1,%2,%3}, {%4,%5,%6,%7}, {%8,%9}, {%0,%1,%2,%3};"
        : "+f"(c[0]), "+f"(c[1]), "+f"(c[2]), "+f"(c[3])
        : "r"(a[0]), "r"(a[1]), "r"(a[2]), "r"(a[3]), "r"(b0), "r"(b1));
}
// MUFU cosine (hardware SFU): ~4e-7 abs error on |x| <= pi; we always reduce first.
__device__ __forceinline__ float cos_mufu(float x) {
    float r;
    asm("cos.approx.f32 %0, %1;" : "=f"(r) : "f"(x));
    return r;
}

// ---------------------------------------------------------------------------
// Prep: one warp per row; lane computes 8 consecutive r as fp16,
// stores one uint4 (8 halves) — fully coalesced 512 B/warp stores.
__global__ void __launch_bounds__(256) k_prep(const float* __restrict__ wr,
                                              const float* __restrict__ wrb,
                                              const float* __restrict__ we) {
    int blk  = blockIdx.x;
    int wid  = threadIdx.x >> 5;
    int lane = threadIdx.x & 31;
    int r0 = lane * 8;

    float v[8];
    size_t dst;
    if (blk < RED_BLKS) {
        int q  = blk * 8 + wid;
        int qc = min(q, NQ - 1);                  // pad rows clamped (never stored)
        float tq = (float)qc * 0.1f;              // matches floor(t/0.1f)*0.1f
        float4 w0 = *(const float4*)(wr + r0);
        float4 w1 = *(const float4*)(wr + r0 + 4);
        float4 b0 = *(const float4*)(wrb + r0);
        float4 b1 = *(const float4*)(wrb + r0 + 4);
        float ws[8] = { w0.x, w0.y, w0.z, w0.w, w1.x, w1.y, w1.z, w1.w };
        float bs[8] = { b0.x, b0.y, b0.z, b0.w, b1.x, b1.y, b1.z, b1.w };
#pragma unroll
        for (int j = 0; j < 8; ++j) {
            float arg = fmaf(tq, ws[j], bs[j]);
            // Cody-Waite 2*pi reduction (|arg| <= ~153): exact under fast-math
            float k   = rintf(arg * 0.15915494309189535f);
            float red = fmaf(-k, 6.28125f, arg);
            red       = fmaf(-k, 1.9353071795864769e-3f, red);
            float c   = cos_mufu(red);
            v[j] = c > 0.0f ? c : 0.0f;
        }
        dst = (size_t)q * RR + r0;
    } else {
        int d = (blk - RED_BLKS) * 8 + wid;
        const float4* p = (const float4*)(we + (size_t)d * RR + r0);
        float4 x0 = p[0], x1 = p[1];
        v[0] = x0.x; v[1] = x0.y; v[2] = x0.z; v[3] = x0.w;
        v[4] = x1.x; v[5] = x1.y; v[6] = x1.z; v[7] = x1.w;
        dst = (size_t)d * RR + r0;
    }

    uint4 pk;
    uint32_t* pw = (uint32_t*)&pk;
#pragma unroll
    for (int j = 0; j < 4; ++j) {
        __half2 h = __floats2half2_rn(v[2 * j], v[2 * j + 1]);
        pw[j] = *(const uint32_t*)&h;
    }
    if (blk < RED_BLKS) *(uint4*)(g_redF + dst) = pk;
    else                *(uint4*)(g_WeF  + dst) = pk;
}

// ---------------------------------------------------------------------------
// HMMA table build, single fp16 product: four-stage K=64 (28 KB smem,
// 4 CTAs/SM). 8 warps (4m x 2n); warp tile 32q x 32d.
// grid (79, 16), 256 threads.
__global__ void __launch_bounds__(256) k_mma_table(const float* __restrict__ web) {
    extern __shared__ char dsm[];
    __shared__ float sWeb[DT];
    uint32_t sb = smem_u32(dsm);
    int tid = threadIdx.x, lane = tid & 31, wid = tid >> 5;
    int qt0 = blockIdx.x * QT, dt0 = blockIdx.y * DT;

    if (tid < DT) sWeb[tid] = web[dt0 + tid];

    int wm = wid & 3, wn = wid >> 2;
    int lrow  = lane & 15;
    int khalf = (lane >> 4) * 8;

    uint32_t aB = sb + OFF_A + (uint32_t)((wm * 32 + lrow) * SP2 + khalf) * 2;
    uint32_t bB = sb + OFF_B + (uint32_t)((wn * 32 + lrow) * SP2 + khalf) * 2;

    float acc[2][4][4];
#pragma unroll
    for (int m = 0; m < 2; ++m)
#pragma unroll
        for (int j = 0; j < 4; ++j)
#pragma unroll
            for (int c = 0; c < 4; ++c) acc[m][j][c] = 0.0f;

    for (int h = 0; h < 4; ++h) {
        if (h) __syncthreads();            // protect smem reuse across stages

        // stage K quarter h: A 128x64 fp16, B 64x64 fp16
#pragma unroll 4
        for (int i = tid; i < QT * 8; i += 256) {
            int row = i >> 3, u = i & 7;
            size_t   src = (size_t)(qt0 + row) * RR + h * 64 + u * 8;
            uint32_t dst = (uint32_t)(row * SP2 + u * 8) * 2;
            *(uint4*)(dsm + OFF_A + dst) = *(const uint4*)(g_redF + src);
        }
#pragma unroll 2
        for (int i = tid; i < DT * 8; i += 256) {
            int row = i >> 3, u = i & 7;
            size_t   src = (size_t)(dt0 + row) * RR + h * 64 + u * 8;
            uint32_t dst = (uint32_t)(row * SP2 + u * 8) * 2;
            *(uint4*)(dsm + OFF_B + dst) = *(const uint4*)(g_WeF + src);
        }
        __syncthreads();

#pragma unroll
        for (int ks = 0; ks < 4; ++ks) {
            uint32_t ko = (uint32_t)(ks * 16) * 2;
            uint32_t aF[2][4], bF[2][4];
            ldm4(aF[0], aB + ko);
            ldm4(aF[1], aB + ko + 16 * SP2 * 2);
            ldm4(bF[0], bB + ko);
            ldm4(bF[1], bB + ko + 16 * SP2 * 2);
#pragma unroll
            for (int m = 0; m < 2; ++m) {
#pragma unroll
                for (int j = 0; j < 4; ++j) {
                    int g = j >> 1, p = j & 1;
                    mma_f16(acc[m][j], aF[m], bF[g][p], bF[g][p + 2]);
                }
            }
        }
    }

    // Epilogue: +bias, convert to fp16, half2 stores.
    int crow = lane >> 2;
    int ccol = (lane & 3) * 2;
#pragma unroll
    for (int m = 0; m < 2; ++m) {
        int r0 = qt0 + wm * 32 + m * 16 + crow;
#pragma unroll
        for (int j = 0; j < 4; ++j) {
            int cl = wn * 32 + j * 8 + ccol;
            float b0 = sWeb[cl], b1 = sWeb[cl + 1];
            if (r0 < NQ) {
                __half2 o = __floats2half2_rn(acc[m][j][0] + b0, acc[m][j][1] + b1);
                *(__half2*)(g_table + (size_t)r0 * DD + dt0 + cl) = o;
            }
            if (r0 + 8 < NQ) {
                __half2 o = __floats2half2_rn(acc[m][j][2] + b0, acc[m][j][3] + b1);
                *(__half2*)(g_table + (size_t)(r0 + 8) * DD + dt0 + cl) = o;
            }
        }
    }
}

// ---------------------------------------------------------------------------
// Scatter (proven form): out[b][:] = fp32(table_fp16[q(b)][:])
// 8 rows/block, 256 threads; 8 independent 8B loads, cvt, 8 STG.128 streaming.
__global__ void __launch_bounds__(256) k_scatter(const float* __restrict__ tt,
                                                 float4* __restrict__ out) {
    __shared__ int qidx[ROWS_PER_BLK];
    int b0 = blockIdx.x * ROWS_PER_BLK;
    if (threadIdx.x < ROWS_PER_BLK) {
        float tv = __ldg(tt + b0 + threadIdx.x);
        int q = (int)floorf(__fdiv_rn(tv, 0.1f));   // IEEE div under any fast-math
        qidx[threadIdx.x] = max(0, min(q, NQ - 1));
    }
    __syncthreads();

    const uint2* tab = (const uint2*)g_table;       // 4 halves per uint2
    uint2 v[ROWS_PER_BLK];
#pragma unroll
    for (int i = 0; i < ROWS_PER_BLK; ++i)
        v[i] = tab[(size_t)qidx[i] * (DD / 4) + threadIdx.x];
#pragma unroll
    for (int i = 0; i < ROWS_PER_BLK; ++i) {
        float2 f01 = __half22float2(*(const __half2*)&v[i].x);
        float2 f23 = __half22float2(*(const __half2*)&v[i].y);
        float4 o = { f01.x, f01.y, f23.x, f23.y };
        __stcs(out + ((size_t)(b0 + i) * (DD / 4) + threadIdx.x), o);
    }
}

// ---------------------------------------------------------------------------
extern "C" void kernel_launch(void* const* d_in, const int* in_sizes, int n_in,
                              void* d_out, int out_size) {
    const float* t   = (const float*)d_in[0];   // (B,)
    const float* wr  = (const float*)d_in[1];   // (R,1)
    const float* wrb = (const float*)d_in[2];   // (R,)
    const float* we  = (const float*)d_in[3];   // (D,R)
    const float* web = (const float*)d_in[4];   // (D,)
    float* out = (float*)d_out;
    int B = in_sizes[0];

    cudaFuncSetAttribute(k_mma_table,
                         cudaFuncAttributeMaxDynamicSharedMemorySize, SMEM_MMA);

    k_prep<<<RED_BLKS + WE_BLKS, 256>>>(wr, wrb, we);
    k_mma_table<<<dim3(NQT / QT, DD / DT), 256, SMEM_MMA>>>(web);
    k_scatter<<<B / ROWS_PER_BLK, 256>>>(t, (float4*)out);
}